// round 16
// baseline (speedup 1.0000x reference)
#include <cuda_runtime.h>
#include <cuda_bf16.h>
#include <cstdint>
#include <cstddef>

// ---------------- problem constants ----------------
#define Q_ROWS  4096
#define N_ROWS  50000
#define K_CODES 1024
#define D_DIM   256
#define NTILES_N 391                 // ceil(50000/128)
#define QN ((size_t)Q_ROWS * N_ROWS)
#define NFIX_BLOCKS 6250             // ceil(50000/8) fixup blocks
#define NCAND 6                      // rescue candidates per row

// ---------------- bf16 (hi-only) ----------------
#define XE_ROWS 50048                // 391*128
#define ROWB    (D_DIM * 2)          // 512 bytes per row

// scratch float-offsets inside d_out (overwritten last by fused_score)
#define XE_OFF_F    65536            // Xe bf16 [50048][256] -> 6,406,144 floats
#define CE_OFF_F    6471680          // Ce bf16 [1024][256]  -> 131,072 floats
#define CAND_OFF_F  6602752          // NCAND arrays of 50048 floats
#define PART_OFF_F  6903040          // fixup partials [6250]

// ---------------- argmin mma smem (bytes): c2 4KB | A 64KB | B0 64KB | B1 64KB ----------------
#define AM_C2   0
#define AM_A    4096
#define AM_B0   69632
#define AM_B1   135168
#define AM_SMEM_B 200704

// ---------------- fused S+gather tiling (proven in R9) ----------------
#define FQ 16
#define FS_AQ_F   (FQ * D_DIM)
#define FS_BROW   20
#define FS_BBUF_F (K_CODES * FS_BROW)
#define FS_SMEM_F (FS_AQ_F + FS_BBUF_F)
#define FS_SMEM_B (FS_SMEM_F * 4)      // 98304 B

// ---------------- helpers ----------------
__device__ __forceinline__ uint32_t smem_u32(const void* p) {
    uint32_t a;
    asm("{ .reg .u64 t; cvta.to.shared.u64 t, %1; cvt.u32.u64 %0, t; }" : "=r"(a) : "l"(p));
    return a;
}
__device__ __forceinline__ void cpa16(uint32_t dst, const void* src) {
    asm volatile("cp.async.cg.shared.global [%0], [%1], 16;\n" :: "r"(dst), "l"(src));
}
__device__ __forceinline__ void cpa_commit() { asm volatile("cp.async.commit_group;\n"); }
__device__ __forceinline__ void cpa_wait0()  { asm volatile("cp.async.wait_group 0;\n"); }

#define LDSM4(r0, r1, r2, r3, addr) \
    asm volatile("ldmatrix.sync.aligned.m8n8.x4.shared.b16 {%0,%1,%2,%3}, [%4];" \
                 : "=r"(r0), "=r"(r1), "=r"(r2), "=r"(r3) : "r"(addr))

#define MMA16816(c, a0, a1, a2, a3, b0, b1) \
    asm volatile("mma.sync.aligned.m16n8k16.row.col.f32.bf16.bf16.f32 " \
                 "{%0,%1,%2,%3}, {%4,%5,%6,%7}, {%8,%9}, {%0,%1,%2,%3};" \
                 : "+f"((c)[0]), "+f"((c)[1]), "+f"((c)[2]), "+f"((c)[3]) \
                 : "r"(a0), "r"(a1), "r"(a2), "r"(a3), "r"(b0), "r"(b1))

// sorted top-NCAND insert (ascending)
__device__ __forceinline__ void topk_update(float v, int c, float* tv, int* ti) {
    if (v >= tv[NCAND - 1]) return;
    int pos = NCAND - 1;
#pragma unroll
    for (int k = NCAND - 2; k >= 0; k--) {
        if (v < tv[k]) pos = k;
    }
#pragma unroll
    for (int k = NCAND - 1; k > 0; k--) {
        if (k > pos) { tv[k] = tv[k - 1]; ti[k] = ti[k - 1]; }
    }
    tv[pos] = v; ti[pos] = c;
}

// ---------------- kernel 1: row squared-norms ----------------
__global__ void __launch_bounds__(256)
rownorm_kernel(const float* __restrict__ A, int rows, float* __restrict__ outp) {
    int row = blockIdx.x * 8 + (threadIdx.x >> 5);
    int lane = threadIdx.x & 31;
    if (row >= rows) return;
    const float4* p = (const float4*)(A + (size_t)row * D_DIM);
    float s = 0.f;
#pragma unroll
    for (int i = 0; i < 2; i++) {
        float4 v = p[lane + 32 * i];
        s += v.x * v.x + v.y * v.y + v.z * v.z + v.w * v.w;
    }
#pragma unroll
    for (int o = 16; o; o >>= 1) s += __shfl_xor_sync(0xFFFFFFFFu, s, o);
    if (lane == 0) outp[row] = s;
}

// ---------------- kernel 2: fp32 -> bf16 (hi only) ----------------
__global__ void __launch_bounds__(256)
convert_kernel(const float* __restrict__ src, unsigned short* __restrict__ dst,
               int rowsValid, int rowsTotal) {
    long long id = (long long)blockIdx.x * 256 + threadIdx.x;   // one per 8 floats
    int row = (int)(id >> 5);
    int seg = (int)(id & 31);
    if (row >= rowsTotal) return;
    float v[8];
    if (row < rowsValid) {
        const float4* p = (const float4*)(src + (size_t)row * D_DIM + seg * 8);
        float4 a = p[0], b = p[1];
        v[0] = a.x; v[1] = a.y; v[2] = a.z; v[3] = a.w;
        v[4] = b.x; v[5] = b.y; v[6] = b.z; v[7] = b.w;
    } else {
#pragma unroll
        for (int i = 0; i < 8; i++) v[i] = 0.f;
    }
    uint32_t hu[4];
#pragma unroll
    for (int i = 0; i < 4; i++) {
        __nv_bfloat16 h0 = __float2bfloat16(v[2 * i]);
        __nv_bfloat16 h1 = __float2bfloat16(v[2 * i + 1]);
        unsigned short h0u = *(unsigned short*)&h0, h1u = *(unsigned short*)&h1;
        hu[i] = (uint32_t)h0u | ((uint32_t)h1u << 16);
    }
    *(uint4*)(dst + (size_t)row * D_DIM + seg * 8) = make_uint4(hu[0], hu[1], hu[2], hu[3]);
}

// ---------------- kernel 3: mma.sync bf16 top-6 candidate search ----------------
// CTA = 256 threads (8 warps x 16 rows). Full A panel (128 rows x 512 B) resident
// in smem; B tiles (128 codes x 512 B) double-buffered across the 8 cc chunks.
__global__ void __launch_bounds__(256)
argmin_mma_kernel(const unsigned short* __restrict__ Xe, const unsigned short* __restrict__ Ce,
                  const float* __restrict__ c2p, float* __restrict__ candp) {
    extern __shared__ char smc[];
    uint32_t sbase = smem_u32(smc);
    int tid = threadIdx.x;
    int lane = tid & 31, w = tid >> 5;           // w = 0..7
    int rowbase = blockIdx.x * 128;

    float* c2s = (float*)(smc + AM_C2);
    for (int i = tid; i < K_CODES; i += 256) c2s[i] = c2p[i];

    const char* XeB = (const char*)Xe;
    const char* CeB = (const char*)Ce;
    uint32_t smA = sbase + AM_A;
    uint32_t smB[2] = { sbase + AM_B0, sbase + AM_B1 };

    // ---- issue A panel (64KB) + B tile 0 (64KB) ----
#pragma unroll
    for (int it = 0; it < 16; it++) {
        int id = tid + 256 * it;          // 0..4095 segs of 16B
        int row = id >> 5, s = id & 31;
        cpa16(smA + (uint32_t)(row * 512 + ((s * 16) ^ ((row & 7) * 16))),
              XeB + (size_t)(rowbase + row) * ROWB + s * 16);
    }
#pragma unroll
    for (int it = 0; it < 16; it++) {
        int id = tid + 256 * it;
        int row = id >> 5, s = id & 31;
        cpa16(smB[0] + (uint32_t)(row * 512 + ((s * 16) ^ ((row & 7) * 16))),
              CeB + (size_t)row * ROWB + s * 16);
    }
    cpa_commit();

    // per-lane ldmatrix fragment coordinates (identical mapping to R13/R14)
    int g = lane >> 3;
    int arow = 16 * w + ((g & 1) ? 8 : 0) + (lane & 7);
    uint32_t akoff = (g >= 2) ? 16u : 0u;
    uint32_t amask = (uint32_t)((arow & 7) * 16);
    int brow_base = ((g >= 2) ? 8 : 0) + (lane & 7);
    uint32_t bkoff = (uint32_t)((g & 1) * 16);

    // top-6 state for 2 owned rows (r0 = 16w + lane>>2, r1 = r0+8)
    float tv[2][NCAND];
    int   ti[2][NCAND];
#pragma unroll
    for (int h = 0; h < 2; h++)
#pragma unroll
        for (int k = 0; k < NCAND; k++) { tv[h][k] = 3.0e38f; ti[h][k] = 0; }

    for (int cc = 0; cc < 8; cc++) {
        cpa_wait0();          // B[cc] (and A on cc==0) complete
        __syncthreads();      // visible to all warps; prior compute done

        if (cc + 1 < 8) {
#pragma unroll
            for (int it = 0; it < 16; it++) {
                int id = tid + 256 * it;
                int row = id >> 5, s = id & 31;
                cpa16(smB[(cc + 1) & 1] + (uint32_t)(row * 512 + ((s * 16) ^ ((row & 7) * 16))),
                      CeB + (size_t)((cc + 1) * 128 + row) * ROWB + s * 16);
            }
            cpa_commit();
        }

        float acc[16][4];
#pragma unroll
        for (int j = 0; j < 16; j++)
#pragma unroll
            for (int r = 0; r < 4; r++) acc[j][r] = 0.f;

        uint32_t bT = smB[cc & 1];
#pragma unroll
        for (int kc = 0; kc < 4; kc++) {
#pragma unroll
            for (int ks = 0; ks < 4; ks++) {
                uint32_t kbyteA = (uint32_t)(kc * 128 + ks * 32) + akoff;
                uint32_t a0, a1, a2, a3;
                uint32_t aaddr = smA + (uint32_t)(arow * 512) + (kbyteA ^ amask);
                LDSM4(a0, a1, a2, a3, aaddr);
                uint32_t kbyteB = (uint32_t)(kc * 128 + ks * 32) + bkoff;
#pragma unroll
                for (int t = 0; t < 8; t++) {
                    int brow = 16 * t + brow_base;
                    uint32_t bmask = (uint32_t)((brow & 7) * 16);
                    uint32_t baddr = bT + (uint32_t)(brow * 512) + (kbyteB ^ bmask);
                    uint32_t b0, b1, b2, b3;
                    LDSM4(b0, b1, b2, b3, baddr);
                    MMA16816(acc[2 * t],     a0, a1, a2, a3, b0, b1);
                    MMA16816(acc[2 * t + 1], a0, a1, a2, a3, b2, b3);
                }
            }
        }

        // epilogue: v = c2[code] - 2*dot; top-6 update per owned row
        int colb = 2 * (lane & 3);
#pragma unroll
        for (int j = 0; j < 16; j++) {
            int code = cc * 128 + 8 * j + colb;
            float c2a = c2s[code], c2b = c2s[code + 1];
            topk_update(c2a - 2.0f * acc[j][0], code,     tv[0], ti[0]);
            topk_update(c2b - 2.0f * acc[j][1], code + 1, tv[0], ti[0]);
            topk_update(c2a - 2.0f * acc[j][2], code,     tv[1], ti[1]);
            topk_update(c2b - 2.0f * acc[j][3], code + 1, tv[1], ti[1]);
        }
    }

    // quad reduce top-6 (lanes sharing lane>>2 hold the same rows)
#pragma unroll
    for (int off = 1; off <= 2; off <<= 1) {
#pragma unroll
        for (int h = 0; h < 2; h++) {
#pragma unroll
            for (int k = 0; k < NCAND; k++) {
                float ov = __shfl_xor_sync(0xFFFFFFFFu, tv[h][k], off);
                int   oi = __shfl_xor_sync(0xFFFFFFFFu, ti[h][k], off);
                topk_update(ov, oi, tv[h], ti[h]);
            }
        }
    }

    if ((lane & 3) == 0) {
#pragma unroll
        for (int h = 0; h < 2; h++) {
            int r = rowbase + 16 * w + (lane >> 2) + 8 * h;
#pragma unroll
            for (int k = 0; k < NCAND; k++)
                candp[(size_t)k * XE_ROWS + r] = (float)ti[h][k];
        }
    }
}

// ---------------- kernel 4: exact fp32 fixup of top-6 candidates + vq partials ----------------
__global__ void __launch_bounds__(256)
fixup_kernel(const float* __restrict__ X, const float* __restrict__ C,
             const float* __restrict__ c2p, const float* __restrict__ x2p,
             const float* __restrict__ candp,
             float* __restrict__ partp, float* __restrict__ idxFp) {
    __shared__ float wsum[8];
    int lane = threadIdx.x & 31, w = threadIdx.x >> 5;
    int row = blockIdx.x * 8 + w;
    float contrib = 0.f;
    if (row < N_ROWS) {
        int cand[NCAND];
#pragma unroll
        for (int k = 0; k < NCAND; k++)
            cand[k] = (int)(candp[(size_t)k * XE_ROWS + row] + 0.5f);
        const float4* xr = (const float4*)(X + (size_t)row * D_DIM);
        float4 xv0 = xr[lane], xv1 = xr[lane + 32];
        float bv = 3.0e38f;
        int   bi = 0;
#pragma unroll
        for (int k = 0; k < NCAND; k++) {
            int c = cand[k];
            const float4* cr = (const float4*)(C + (size_t)c * D_DIM);
            float4 c0 = cr[lane], c1 = cr[lane + 32];
            float d = xv0.x * c0.x + xv0.y * c0.y + xv0.z * c0.z + xv0.w * c0.w
                    + xv1.x * c1.x + xv1.y * c1.y + xv1.z * c1.z + xv1.w * c1.w;
#pragma unroll
            for (int o = 16; o; o >>= 1) d += __shfl_xor_sync(0xFFFFFFFFu, d, o);
            float v = c2p[c] - 2.0f * d;
            if (v < bv || (v == bv && c < bi)) { bv = v; bi = c; }
        }
        if (lane == 0) {
            idxFp[row] = (float)bi;
            contrib = x2p[row] + bv;
        }
    }
    if (lane == 0) wsum[w] = contrib;
    __syncthreads();
    if (threadIdx.x == 0) {
        float s = 0.f;
#pragma unroll
        for (int i = 0; i < 8; i++) s += wsum[i];
        partp[blockIdx.x] = s;
    }
}

// ---------------- kernel 5: vq_loss finalize ----------------
__global__ void __launch_bounds__(256)
finalize_kernel(const float* __restrict__ partp, float* __restrict__ lossp, int writeLoss) {
    __shared__ float s[256];
    int tid = threadIdx.x;
    float v = 0.f;
    for (int i = tid; i < NFIX_BLOCKS; i += 256) v += partp[i];
    s[tid] = v;
    __syncthreads();
    for (int o = 128; o >= 1; o >>= 1) {
        if (tid < o) s[tid] += s[tid + o];
        __syncthreads();
    }
    if (tid == 0 && writeLoss) {
        lossp[0] = 1.25f * s[0] / ((float)N_ROWS * (float)D_DIM);
    }
}

// ---------------- kernel 6: fused S-compute + gather (unchanged from R9) ----------------
__global__ void __launch_bounds__(256)
fused_score_kernel(const float* __restrict__ Qm, const float* __restrict__ Cm,
                   const float* __restrict__ idxFp, float* __restrict__ outp) {
    extern __shared__ float sm[];
    int tid = threadIdx.x;
    int qb = blockIdx.x * FQ;

#pragma unroll
    for (int it = 0; it < 4; it++) {
        int id = tid + 256 * it;
        int row = id >> 6;
        int c4 = id & 63;
        *(float4*)(sm + row * D_DIM + c4 * 4) =
            *(const float4*)(Qm + (size_t)(qb + row) * D_DIM + c4 * 4);
    }

    int qg = tid >> 7;
    int cg = tid & 127;
    int sw = cg & 3;

    float acc[8][8];
#pragma unroll
    for (int i = 0; i < 8; i++)
#pragma unroll
        for (int j = 0; j < 8; j++) acc[i][j] = 0.f;

    uint32_t bbase = smem_u32(sm + FS_AQ_F);

    for (int dc = 0; dc < D_DIM / 16; dc++) {
        __syncthreads();
#pragma unroll
        for (int it = 0; it < 16; it++) {
            int id = tid + 256 * it;
            int code = id >> 2;
            int dg = id & 3;
            int dsw = dg ^ ((code >> 3) & 3);
            cpa16(bbase + (uint32_t)(code * FS_BROW + dsw * 4) * 4,
                  Cm + (size_t)code * D_DIM + dc * 16 + dg * 4);
        }
        cpa_commit();
        cpa_wait0();
        __syncthreads();

        const float* Bb = sm + FS_AQ_F;
#pragma unroll
        for (int kk4 = 0; kk4 < 4; kk4++) {
            int ks = (kk4 ^ sw) << 2;
            float4 b4[8];
#pragma unroll
            for (int j = 0; j < 8; j++)
                b4[j] = *(const float4*)(Bb + (cg * 8 + j) * FS_BROW + ks);
#pragma unroll
            for (int i = 0; i < 8; i++) {
                float4 a4 = *(const float4*)(sm + (qg * 8 + i) * D_DIM + dc * 16 + kk4 * 4);
#pragma unroll
                for (int j = 0; j < 8; j++) {
                    acc[i][j] = fmaf(a4.x, b4[j].x, acc[i][j]);
                    acc[i][j] = fmaf(a4.y, b4[j].y, acc[i][j]);
                    acc[i][j] = fmaf(a4.z, b4[j].z, acc[i][j]);
                    acc[i][j] = fmaf(a4.w, b4[j].w, acc[i][j]);
                }
            }
        }
    }

    __syncthreads();
    float* S = sm + FS_AQ_F;
#pragma unroll
    for (int i = 0; i < 8; i++) {
#pragma unroll
        for (int j4 = 0; j4 < 2; j4++) {
            float4 v = make_float4(acc[i][j4 * 4 + 0], acc[i][j4 * 4 + 1],
                                   acc[i][j4 * 4 + 2], acc[i][j4 * 4 + 3]);
            *(float4*)(S + (qg * 8 + i) * K_CODES + cg * 8 + j4 * 4) = v;
        }
    }
    __syncthreads();

    for (int base = 0; base < N_ROWS; base += 1024) {
        int n = base + (tid << 2);
        if (n < N_ROWS) {
            int i0 = (int)(idxFp[n + 0] + 0.5f);
            int i1 = (int)(idxFp[n + 1] + 0.5f);
            int i2 = (int)(idxFp[n + 2] + 0.5f);
            int i3 = (int)(idxFp[n + 3] + 0.5f);
#pragma unroll
            for (int q = 0; q < FQ; q++) {
                const float* Sr = S + q * K_CODES;
                float4 v = make_float4(Sr[i0], Sr[i1], Sr[i2], Sr[i3]);
                *(float4*)(outp + (size_t)(qb + q) * N_ROWS + n) = v;
            }
        }
    }
}

// ---------------- host launch ----------------
extern "C" void kernel_launch(void* const* d_in, const int* in_sizes, int n_in,
                              void* d_out, int out_size) {
    const float* Qm = nullptr;
    const float* Xm = nullptr;
    const float* Cm = nullptr;
    for (int i = 0; i < n_in; i++) {
        if (in_sizes[i] == Q_ROWS * D_DIM)       Qm = (const float*)d_in[i];
        else if (in_sizes[i] == N_ROWS * D_DIM)  Xm = (const float*)d_in[i];
        else if (in_sizes[i] == K_CODES * D_DIM) Cm = (const float*)d_in[i];
    }
    if (!Qm && n_in > 0) Qm = (const float*)d_in[0];
    if (!Xm && n_in > 1) Xm = (const float*)d_in[1];
    if (!Cm && n_in > 2) Cm = (const float*)d_in[2];

    float* out = (float*)d_out;
    bool hasExtra = ((size_t)out_size >= QN + 1 + N_ROWS);

    // Scratch carved from the score region (overwritten last by fused_score):
    float* c2p   = out;                  // [0, 1024)
    float* x2p   = out + 2048;           // [2048, 52048)
    unsigned short* Xe = (unsigned short*)(out + XE_OFF_F);
    unsigned short* Ce = (unsigned short*)(out + CE_OFF_F);
    float* candp = out + CAND_OFF_F;
    float* partp = out + PART_OFF_F;
    float* idxp  = hasExtra ? (out + QN + 1) : (out + (QN - N_ROWS));
    float* lossp = out + QN;

    (void)cudaFuncSetAttribute(argmin_mma_kernel,  cudaFuncAttributeMaxDynamicSharedMemorySize, AM_SMEM_B);
    (void)cudaFuncSetAttribute(fused_score_kernel, cudaFuncAttributeMaxDynamicSharedMemorySize, FS_SMEM_B);

    // 1. norms
    rownorm_kernel<<<(K_CODES + 7) / 8, 256>>>(Cm, K_CODES, c2p);
    rownorm_kernel<<<(N_ROWS + 7) / 8, 256>>>(Xm, N_ROWS, x2p);

    // 2. bf16 conversions (hi only)
    convert_kernel<<<(XE_ROWS * 32 + 255) / 256, 256>>>(Xm, Xe, N_ROWS, XE_ROWS);
    convert_kernel<<<(K_CODES * 32 + 255) / 256, 256>>>(Cm, Ce, K_CODES, K_CODES);

    // 3. mma.sync top-6 candidate search (A panel resident, B double-buffered)
    argmin_mma_kernel<<<NTILES_N, 256, AM_SMEM_B>>>(Xe, Ce, c2p, candp);

    // 4. exact fp32 fixup over 6 candidates -> nearest_idx + vq partials
    fixup_kernel<<<NFIX_BLOCKS, 256>>>(Xm, Cm, c2p, x2p, candp, partp, idxp);

    // 5. vq_loss
    finalize_kernel<<<1, 256>>>(partp, lossp, hasExtra ? 1 : 0);

    // 6. fused S = Q@C^T + score gather (overwrites all scratch)
    fused_score_kernel<<<Q_ROWS / FQ, 256, FS_SMEM_B>>>(Qm, Cm, idxp, out);
}

// round 17
// speedup vs baseline: 3.0792x; 3.0792x over previous
#include <cuda_runtime.h>
#include <cuda_bf16.h>
#include <cstdint>
#include <cstddef>

// ---------------- problem constants ----------------
#define Q_ROWS  4096
#define N_ROWS  50000
#define K_CODES 1024
#define D_DIM   256
#define NTILES_N 391                 // ceil(50000/128)
#define QN ((size_t)Q_ROWS * N_ROWS)
#define NFIX_BLOCKS 6250             // ceil(50000/8) fixup blocks
#define NCAND 4                      // rescue candidates per row

// ---------------- bf16 (hi-only) ----------------
#define XE_ROWS 50048                // 391*128
#define ROWB    (D_DIM * 2)          // 512 bytes per row
#define NKC     4                    // 4 K-chunks of 64 bf16 (128 B)

// scratch float-offsets inside d_out (overwritten last by fused_score)
#define XE_OFF_F    65536            // Xe bf16 [50048][256] -> 6,406,144 floats
#define CE_OFF_F    6471680          // Ce bf16 [1024][256]  -> 131,072 floats
#define CAND_OFF_F  6602752          // NCAND arrays of 50048 floats
#define PART_OFF_F  6802944          // fixup partials [6250]

// ---------------- argmin mma smem (bytes): c2 4KB | A0/B0/A1/B1 16KB each ----------------
#define AM_C2   0
#define AM_A0   4096
#define AM_B0   20480
#define AM_A1   36864
#define AM_B1   53248
#define AM_SMEM_B 69632

// ---------------- fused S+gather tiling (proven in R9) ----------------
#define FQ 16
#define FS_AQ_F   (FQ * D_DIM)
#define FS_BROW   20
#define FS_BBUF_F (K_CODES * FS_BROW)
#define FS_SMEM_F (FS_AQ_F + FS_BBUF_F)
#define FS_SMEM_B (FS_SMEM_F * 4)      // 98304 B

// ---------------- helpers ----------------
__device__ __forceinline__ uint32_t smem_u32(const void* p) {
    uint32_t a;
    asm("{ .reg .u64 t; cvta.to.shared.u64 t, %1; cvt.u32.u64 %0, t; }" : "=r"(a) : "l"(p));
    return a;
}
__device__ __forceinline__ void cpa16(uint32_t dst, const void* src) {
    asm volatile("cp.async.cg.shared.global [%0], [%1], 16;\n" :: "r"(dst), "l"(src));
}
__device__ __forceinline__ void cpa_commit() { asm volatile("cp.async.commit_group;\n"); }
__device__ __forceinline__ void cpa_wait0()  { asm volatile("cp.async.wait_group 0;\n"); }

#define SWZ128(off) ((off) ^ (((off) >> 3) & 0x70))

#define LDSM4(r0, r1, r2, r3, addr) \
    asm volatile("ldmatrix.sync.aligned.m8n8.x4.shared.b16 {%0,%1,%2,%3}, [%4];" \
                 : "=r"(r0), "=r"(r1), "=r"(r2), "=r"(r3) : "r"(addr))

#define MMA16816(c, a0, a1, a2, a3, b0, b1) \
    asm volatile("mma.sync.aligned.m16n8k16.row.col.f32.bf16.bf16.f32 " \
                 "{%0,%1,%2,%3}, {%4,%5,%6,%7}, {%8,%9}, {%0,%1,%2,%3};" \
                 : "+f"((c)[0]), "+f"((c)[1]), "+f"((c)[2]), "+f"((c)[3]) \
                 : "r"(a0), "r"(a1), "r"(a2), "r"(a3), "r"(b0), "r"(b1))

// top-4 insert, fully unrolled, compile-time indices only (register-resident)
__device__ __forceinline__ void topk_update(float v, int c, float* tv, int* ti) {
    if (v >= tv[3]) return;
    if (v < tv[0]) {
        tv[3] = tv[2]; ti[3] = ti[2];
        tv[2] = tv[1]; ti[2] = ti[1];
        tv[1] = tv[0]; ti[1] = ti[0];
        tv[0] = v;     ti[0] = c;
    } else if (v < tv[1]) {
        tv[3] = tv[2]; ti[3] = ti[2];
        tv[2] = tv[1]; ti[2] = ti[1];
        tv[1] = v;     ti[1] = c;
    } else if (v < tv[2]) {
        tv[3] = tv[2]; ti[3] = ti[2];
        tv[2] = v;     ti[2] = c;
    } else {
        tv[3] = v;     ti[3] = c;
    }
}

// ---------------- kernel 1: row squared-norms ----------------
__global__ void __launch_bounds__(256)
rownorm_kernel(const float* __restrict__ A, int rows, float* __restrict__ outp) {
    int row = blockIdx.x * 8 + (threadIdx.x >> 5);
    int lane = threadIdx.x & 31;
    if (row >= rows) return;
    const float4* p = (const float4*)(A + (size_t)row * D_DIM);
    float s = 0.f;
#pragma unroll
    for (int i = 0; i < 2; i++) {
        float4 v = p[lane + 32 * i];
        s += v.x * v.x + v.y * v.y + v.z * v.z + v.w * v.w;
    }
#pragma unroll
    for (int o = 16; o; o >>= 1) s += __shfl_xor_sync(0xFFFFFFFFu, s, o);
    if (lane == 0) outp[row] = s;
}

// ---------------- kernel 2: fp32 -> bf16 (hi only; validated R16) ----------------
__global__ void __launch_bounds__(256)
convert_kernel(const float* __restrict__ src, unsigned short* __restrict__ dst,
               int rowsValid, int rowsTotal) {
    long long id = (long long)blockIdx.x * 256 + threadIdx.x;   // one per 8 floats
    int row = (int)(id >> 5);
    int seg = (int)(id & 31);
    if (row >= rowsTotal) return;
    float v[8];
    if (row < rowsValid) {
        const float4* p = (const float4*)(src + (size_t)row * D_DIM + seg * 8);
        float4 a = p[0], b = p[1];
        v[0] = a.x; v[1] = a.y; v[2] = a.z; v[3] = a.w;
        v[4] = b.x; v[5] = b.y; v[6] = b.z; v[7] = b.w;
    } else {
#pragma unroll
        for (int i = 0; i < 8; i++) v[i] = 0.f;
    }
    uint32_t hu[4];
#pragma unroll
    for (int i = 0; i < 4; i++) {
        __nv_bfloat16 h0 = __float2bfloat16(v[2 * i]);
        __nv_bfloat16 h1 = __float2bfloat16(v[2 * i + 1]);
        unsigned short h0u = *(unsigned short*)&h0, h1u = *(unsigned short*)&h1;
        hu[i] = (uint32_t)h0u | ((uint32_t)h1u << 16);
    }
    *(uint4*)(dst + (size_t)row * D_DIM + seg * 8) = make_uint4(hu[0], hu[1], hu[2], hu[3]);
}

// ---------------- kernel 3: mma.sync bf16 top-4 candidate search ----------------
// R13 structure verbatim (8 warps x 16 rows, 16KB double-buffered A/B chunks,
// 3 CTAs/SM), with K=256 (4 chunks) and top-4 epilogue.
__device__ __forceinline__ void am_load_stage(uint32_t smA, uint32_t smB,
                                              const char* XeB, const char* CeB,
                                              int rowbase, int cc, int kc, int tid) {
#pragma unroll
    for (int it = 0; it < 4; it++) {
        int idx = tid + 256 * it;
        int row = idx >> 3, seg = idx & 7;
        uint32_t off = (uint32_t)(row * 128 + seg * 16);
        cpa16(smA + SWZ128(off), XeB + (size_t)(rowbase + row) * ROWB + kc * 128 + seg * 16);
    }
#pragma unroll
    for (int it = 0; it < 4; it++) {
        int idx = tid + 256 * it;
        int row = idx >> 3, seg = idx & 7;
        uint32_t off = (uint32_t)(row * 128 + seg * 16);
        cpa16(smB + SWZ128(off), CeB + (size_t)(cc * 128 + row) * ROWB + kc * 128 + seg * 16);
    }
}

__global__ void __launch_bounds__(256)
argmin_mma_kernel(const unsigned short* __restrict__ Xe, const unsigned short* __restrict__ Ce,
                  const float* __restrict__ c2p, float* __restrict__ candp) {
    extern __shared__ char smc[];
    uint32_t sbase = smem_u32(smc);
    int tid = threadIdx.x;
    int lane = tid & 31, w = tid >> 5;
    int rowbase = blockIdx.x * 128;

    float* c2s = (float*)(smc + AM_C2);
    for (int i = tid; i < K_CODES; i += 256) c2s[i] = c2p[i];

    const char* XeB = (const char*)Xe;
    const char* CeB = (const char*)Ce;
    uint32_t smA[2] = { sbase + AM_A0, sbase + AM_A1 };
    uint32_t smB[2] = { sbase + AM_B0, sbase + AM_B1 };

    int g = lane >> 3;
    int arow = 16 * w + ((g & 1) ? 8 : 0) + (lane & 7);
    uint32_t akoff = (g >= 2) ? 16u : 0u;
    uint32_t amask = (uint32_t)((arow & 7) * 16);
    int brow_base = ((g >= 2) ? 8 : 0) + (lane & 7);
    uint32_t bkoff = (uint32_t)((g & 1) * 16);

    // top-4 state for 2 owned rows (r0 = 16w + lane>>2, r1 = r0+8)
    float tv[2][NCAND];
    int   ti[2][NCAND];
#pragma unroll
    for (int h = 0; h < 2; h++)
#pragma unroll
        for (int k = 0; k < NCAND; k++) { tv[h][k] = 3.0e38f; ti[h][k] = 0; }

    for (int cc = 0; cc < 8; cc++) {
        float acc[16][4];
#pragma unroll
        for (int j = 0; j < 16; j++)
#pragma unroll
            for (int r = 0; r < 4; r++) acc[j][r] = 0.f;

        __syncthreads();   // prior cc's buffers fully consumed; c2s ready on first iter
        am_load_stage(smA[0], smB[0], XeB, CeB, rowbase, cc, 0, tid);
        cpa_commit();

        for (int kc = 0; kc < NKC; kc++) {
            cpa_wait0();
            __syncthreads();
            if (kc + 1 < NKC) {
                am_load_stage(smA[(kc + 1) & 1], smB[(kc + 1) & 1], XeB, CeB, rowbase, cc, kc + 1, tid);
                cpa_commit();
            }
            uint32_t aT = smA[kc & 1], bT = smB[kc & 1];
#pragma unroll
            for (int ks = 0; ks < 4; ks++) {
                uint32_t a0, a1, a2, a3;
                uint32_t aaddr = aT + (uint32_t)(arow * 128) + (((uint32_t)(ks * 32) + akoff) ^ amask);
                LDSM4(a0, a1, a2, a3, aaddr);
#pragma unroll
                for (int t = 0; t < 8; t++) {
                    int brow = 16 * t + brow_base;
                    uint32_t bmask = (uint32_t)((brow & 7) * 16);
                    uint32_t baddr = bT + (uint32_t)(brow * 128) + (((uint32_t)(ks * 32) + bkoff) ^ bmask);
                    uint32_t b0, b1, b2, b3;
                    LDSM4(b0, b1, b2, b3, baddr);
                    MMA16816(acc[2 * t],     a0, a1, a2, a3, b0, b1);
                    MMA16816(acc[2 * t + 1], a0, a1, a2, a3, b2, b3);
                }
            }
            __syncthreads();
        }

        // epilogue: v = c2[code] - 2*dot; top-4 update per owned row
        int colb = 2 * (lane & 3);
#pragma unroll
        for (int j = 0; j < 16; j++) {
            int code = cc * 128 + 8 * j + colb;
            float c2a = c2s[code], c2b = c2s[code + 1];
            topk_update(c2a - 2.0f * acc[j][0], code,     tv[0], ti[0]);
            topk_update(c2b - 2.0f * acc[j][1], code + 1, tv[0], ti[0]);
            topk_update(c2a - 2.0f * acc[j][2], code,     tv[1], ti[1]);
            topk_update(c2b - 2.0f * acc[j][3], code + 1, tv[1], ti[1]);
        }
    }

    // quad reduce top-4 (lanes sharing lane>>2 hold the same rows)
#pragma unroll
    for (int off = 1; off <= 2; off <<= 1) {
#pragma unroll
        for (int h = 0; h < 2; h++) {
#pragma unroll
            for (int k = 0; k < NCAND; k++) {
                float ov = __shfl_xor_sync(0xFFFFFFFFu, tv[h][k], off);
                int   oi = __shfl_xor_sync(0xFFFFFFFFu, ti[h][k], off);
                topk_update(ov, oi, tv[h], ti[h]);
            }
        }
    }

    if ((lane & 3) == 0) {
#pragma unroll
        for (int h = 0; h < 2; h++) {
            int r = rowbase + 16 * w + (lane >> 2) + 8 * h;
#pragma unroll
            for (int k = 0; k < NCAND; k++)
                candp[(size_t)k * XE_ROWS + r] = (float)ti[h][k];
        }
    }
}

// ---------------- kernel 4: exact fp32 fixup of top-4 candidates + vq partials ----------------
__global__ void __launch_bounds__(256)
fixup_kernel(const float* __restrict__ X, const float* __restrict__ C,
             const float* __restrict__ c2p, const float* __restrict__ x2p,
             const float* __restrict__ candp,
             float* __restrict__ partp, float* __restrict__ idxFp) {
    __shared__ float wsum[8];
    int lane = threadIdx.x & 31, w = threadIdx.x >> 5;
    int row = blockIdx.x * 8 + w;
    float contrib = 0.f;
    if (row < N_ROWS) {
        int cand[NCAND];
#pragma unroll
        for (int k = 0; k < NCAND; k++)
            cand[k] = (int)(candp[(size_t)k * XE_ROWS + row] + 0.5f);
        const float4* xr = (const float4*)(X + (size_t)row * D_DIM);
        float4 xv0 = xr[lane], xv1 = xr[lane + 32];
        float bv = 3.0e38f;
        int   bi = 0;
#pragma unroll
        for (int k = 0; k < NCAND; k++) {
            int c = cand[k];
            const float4* cr = (const float4*)(C + (size_t)c * D_DIM);
            float4 c0 = cr[lane], c1 = cr[lane + 32];
            float d = xv0.x * c0.x + xv0.y * c0.y + xv0.z * c0.z + xv0.w * c0.w
                    + xv1.x * c1.x + xv1.y * c1.y + xv1.z * c1.z + xv1.w * c1.w;
#pragma unroll
            for (int o = 16; o; o >>= 1) d += __shfl_xor_sync(0xFFFFFFFFu, d, o);
            float v = c2p[c] - 2.0f * d;
            if (v < bv || (v == bv && c < bi)) { bv = v; bi = c; }
        }
        if (lane == 0) {
            idxFp[row] = (float)bi;
            contrib = x2p[row] + bv;
        }
    }
    if (lane == 0) wsum[w] = contrib;
    __syncthreads();
    if (threadIdx.x == 0) {
        float s = 0.f;
#pragma unroll
        for (int i = 0; i < 8; i++) s += wsum[i];
        partp[blockIdx.x] = s;
    }
}

// ---------------- kernel 5: vq_loss finalize ----------------
__global__ void __launch_bounds__(256)
finalize_kernel(const float* __restrict__ partp, float* __restrict__ lossp, int writeLoss) {
    __shared__ float s[256];
    int tid = threadIdx.x;
    float v = 0.f;
    for (int i = tid; i < NFIX_BLOCKS; i += 256) v += partp[i];
    s[tid] = v;
    __syncthreads();
    for (int o = 128; o >= 1; o >>= 1) {
        if (tid < o) s[tid] += s[tid + o];
        __syncthreads();
    }
    if (tid == 0 && writeLoss) {
        lossp[0] = 1.25f * s[0] / ((float)N_ROWS * (float)D_DIM);
    }
}

// ---------------- kernel 6: fused S-compute + gather (unchanged from R9) ----------------
__global__ void __launch_bounds__(256)
fused_score_kernel(const float* __restrict__ Qm, const float* __restrict__ Cm,
                   const float* __restrict__ idxFp, float* __restrict__ outp) {
    extern __shared__ float sm[];
    int tid = threadIdx.x;
    int qb = blockIdx.x * FQ;

#pragma unroll
    for (int it = 0; it < 4; it++) {
        int id = tid + 256 * it;
        int row = id >> 6;
        int c4 = id & 63;
        *(float4*)(sm + row * D_DIM + c4 * 4) =
            *(const float4*)(Qm + (size_t)(qb + row) * D_DIM + c4 * 4);
    }

    int qg = tid >> 7;
    int cg = tid & 127;
    int sw = cg & 3;

    float acc[8][8];
#pragma unroll
    for (int i = 0; i < 8; i++)
#pragma unroll
        for (int j = 0; j < 8; j++) acc[i][j] = 0.f;

    uint32_t bbase = smem_u32(sm + FS_AQ_F);

    for (int dc = 0; dc < D_DIM / 16; dc++) {
        __syncthreads();
#pragma unroll
        for (int it = 0; it < 16; it++) {
            int id = tid + 256 * it;
            int code = id >> 2;
            int dg = id & 3;
            int dsw = dg ^ ((code >> 3) & 3);
            cpa16(bbase + (uint32_t)(code * FS_BROW + dsw * 4) * 4,
                  Cm + (size_t)code * D_DIM + dc * 16 + dg * 4);
        }
        cpa_commit();
        cpa_wait0();
        __syncthreads();

        const float* Bb = sm + FS_AQ_F;
#pragma unroll
        for (int kk4 = 0; kk4 < 4; kk4++) {
            int ks = (kk4 ^ sw) << 2;
            float4 b4[8];
#pragma unroll
            for (int j = 0; j < 8; j++)
                b4[j] = *(const float4*)(Bb + (cg * 8 + j) * FS_BROW + ks);
#pragma unroll
            for (int i = 0; i < 8; i++) {
                float4 a4 = *(const float4*)(sm + (qg * 8 + i) * D_DIM + dc * 16 + kk4 * 4);
#pragma unroll
                for (int j = 0; j < 8; j++) {
                    acc[i][j] = fmaf(a4.x, b4[j].x, acc[i][j]);
                    acc[i][j] = fmaf(a4.y, b4[j].y, acc[i][j]);
                    acc[i][j] = fmaf(a4.z, b4[j].z, acc[i][j]);
                    acc[i][j] = fmaf(a4.w, b4[j].w, acc[i][j]);
                }
            }
        }
    }

    __syncthreads();
    float* S = sm + FS_AQ_F;
#pragma unroll
    for (int i = 0; i < 8; i++) {
#pragma unroll
        for (int j4 = 0; j4 < 2; j4++) {
            float4 v = make_float4(acc[i][j4 * 4 + 0], acc[i][j4 * 4 + 1],
                                   acc[i][j4 * 4 + 2], acc[i][j4 * 4 + 3]);
            *(float4*)(S + (qg * 8 + i) * K_CODES + cg * 8 + j4 * 4) = v;
        }
    }
    __syncthreads();

    for (int base = 0; base < N_ROWS; base += 1024) {
        int n = base + (tid << 2);
        if (n < N_ROWS) {
            int i0 = (int)(idxFp[n + 0] + 0.5f);
            int i1 = (int)(idxFp[n + 1] + 0.5f);
            int i2 = (int)(idxFp[n + 2] + 0.5f);
            int i3 = (int)(idxFp[n + 3] + 0.5f);
#pragma unroll
            for (int q = 0; q < FQ; q++) {
                const float* Sr = S + q * K_CODES;
                float4 v = make_float4(Sr[i0], Sr[i1], Sr[i2], Sr[i3]);
                *(float4*)(outp + (size_t)(qb + q) * N_ROWS + n) = v;
            }
        }
    }
}

// ---------------- host launch ----------------
extern "C" void kernel_launch(void* const* d_in, const int* in_sizes, int n_in,
                              void* d_out, int out_size) {
    const float* Qm = nullptr;
    const float* Xm = nullptr;
    const float* Cm = nullptr;
    for (int i = 0; i < n_in; i++) {
        if (in_sizes[i] == Q_ROWS * D_DIM)       Qm = (const float*)d_in[i];
        else if (in_sizes[i] == N_ROWS * D_DIM)  Xm = (const float*)d_in[i];
        else if (in_sizes[i] == K_CODES * D_DIM) Cm = (const float*)d_in[i];
    }
    if (!Qm && n_in > 0) Qm = (const float*)d_in[0];
    if (!Xm && n_in > 1) Xm = (const float*)d_in[1];
    if (!Cm && n_in > 2) Cm = (const float*)d_in[2];

    float* out = (float*)d_out;
    bool hasExtra = ((size_t)out_size >= QN + 1 + N_ROWS);

    // Scratch carved from the score region (overwritten last by fused_score):
    float* c2p   = out;                  // [0, 1024)
    float* x2p   = out + 2048;           // [2048, 52048)
    unsigned short* Xe = (unsigned short*)(out + XE_OFF_F);
    unsigned short* Ce = (unsigned short*)(out + CE_OFF_F);
    float* candp = out + CAND_OFF_F;
    float* partp = out + PART_OFF_F;
    float* idxp  = hasExtra ? (out + QN + 1) : (out + (QN - N_ROWS));
    float* lossp = out + QN;

    (void)cudaFuncSetAttribute(argmin_mma_kernel,  cudaFuncAttributeMaxDynamicSharedMemorySize, AM_SMEM_B);
    (void)cudaFuncSetAttribute(fused_score_kernel, cudaFuncAttributeMaxDynamicSharedMemorySize, FS_SMEM_B);

    // 1. norms
    rownorm_kernel<<<(K_CODES + 7) / 8, 256>>>(Cm, K_CODES, c2p);
    rownorm_kernel<<<(N_ROWS + 7) / 8, 256>>>(Xm, N_ROWS, x2p);

    // 2. bf16 conversions (hi only)
    convert_kernel<<<(XE_ROWS * 32 + 255) / 256, 256>>>(Xm, Xe, N_ROWS, XE_ROWS);
    convert_kernel<<<(K_CODES * 32 + 255) / 256, 256>>>(Cm, Ce, K_CODES, K_CODES);

    // 3. mma.sync top-4 candidate search (R13 structure, K=256)
    argmin_mma_kernel<<<NTILES_N, 256, AM_SMEM_B>>>(Xe, Ce, c2p, candp);

    // 4. exact fp32 fixup over 4 candidates -> nearest_idx + vq partials
    fixup_kernel<<<NFIX_BLOCKS, 256>>>(Xm, Cm, c2p, x2p, candp, partp, idxp);

    // 5. vq_loss
    finalize_kernel<<<1, 256>>>(partp, lossp, hasExtra ? 1 : 0);

    // 6. fused S = Q@C^T + score gather (overwrites all scratch)
    fused_score_kernel<<<Q_ROWS / FQ, 256, FS_SMEM_B>>>(Qm, Cm, idxp, out);
}